// round 1
// baseline (speedup 1.0000x reference)
#include <cuda_runtime.h>

// ---------------------------------------------------------------------------
// EfficientAttention: N=2, D=64, H=W=64, C=64, HEADS=8, hk=hv=8
// token t = c*4096 + h*64 + w  (T = 262144 per batch)
//
// Pass A (per (n,h,w) block, 64 tokens = all c):
//   load X tile (64 d x 64 c), GEMM vs Wq/Wk/Wv (64x64 each),
//   Q: scale/bias/lrelu + softmax over channel-groups of 8 -> g_Q
//   K: scale/bias/lrelu -> exp  (no max-subtraction: keys bounded ~|5|)
//   V: scale/bias/lrelu
//   accumulate ctx_num[a,k,v] += expK[a*8+k]*V[a*8+v], den[a,k] += expK
//   block-partial sums -> fp32 atomicAdd into tiny global accumulators.
// Pass C (per (n,h,w) block):
//   ctx = num/den; load 64 Q rows at r*32768 + h*512 + w*8 + v (8 contiguous
//   2KB chunks); agg[c][a*8+v] = sum_v' ctx[a][c/8][v'] * Q[(c%8)*8+v][a*8+v'];
//   rep = agg @ Wr, scale/bias/lrelu; out[n,d,h,w,c] = x + rep[c][d].
// ---------------------------------------------------------------------------

#define HWDIM   4096
#define T_TOK   262144
#define PLANE   262144            // HWDIM*64 floats per (n,d) plane

__device__ float g_Q[(size_t)2 * T_TOK * 64];   // 128 MiB scratch
__device__ float g_ctxnum[2 * 512];
__device__ float g_den[2 * 64];

__device__ __forceinline__ float lrelu(float y) { return y >= 0.f ? y : 0.2f * y; }

__global__ void zero_acc_kernel() {
    int t = blockIdx.x * blockDim.x + threadIdx.x;
    if (t < 2 * 512) g_ctxnum[t] = 0.f;
    if (t < 2 * 64)  g_den[t]   = 0.f;
}

// 64x64x64 sub-GEMM: out[c][e] = sum_d Xs[d][c] * Ws[d][e]; thread tile 4c x 4e
__device__ __forceinline__ void gemm_tile(const float* __restrict__ Xs,
                                          const float* __restrict__ Ws,
                                          int cg, int eg, float acc[4][4]) {
#pragma unroll
    for (int i = 0; i < 4; i++)
#pragma unroll
        for (int j = 0; j < 4; j++) acc[i][j] = 0.f;
#pragma unroll 8
    for (int d = 0; d < 64; d++) {
        float4 xv = *(const float4*)(Xs + d * 68 + cg);
        float4 wv = *(const float4*)(Ws + d * 68 + eg);
        acc[0][0] += xv.x * wv.x; acc[0][1] += xv.x * wv.y; acc[0][2] += xv.x * wv.z; acc[0][3] += xv.x * wv.w;
        acc[1][0] += xv.y * wv.x; acc[1][1] += xv.y * wv.y; acc[1][2] += xv.y * wv.z; acc[1][3] += xv.y * wv.w;
        acc[2][0] += xv.z * wv.x; acc[2][1] += xv.z * wv.y; acc[2][2] += xv.z * wv.z; acc[2][3] += xv.z * wv.w;
        acc[3][0] += xv.w * wv.x; acc[3][1] += xv.w * wv.y; acc[3][2] += xv.w * wv.z; acc[3][3] += xv.w * wv.w;
    }
}

__device__ __forceinline__ void load_w(float* __restrict__ Ws,
                                       const float* __restrict__ W, int t) {
#pragma unroll
    for (int i = 0; i < 4; i++) {
        int idx = t + i * 256;
        int d = idx >> 4, e4 = (idx & 15) << 2;
        *(float4*)(Ws + d * 68 + e4) = *(const float4*)(W + d * 64 + e4);
    }
}

__global__ void __launch_bounds__(256) passA_kernel(
    const float* __restrict__ x,
    const float* __restrict__ Wk, const float* __restrict__ sk, const float* __restrict__ bk,
    const float* __restrict__ Wq, const float* __restrict__ sq, const float* __restrict__ bq,
    const float* __restrict__ Wv, const float* __restrict__ sv, const float* __restrict__ bv)
{
    extern __shared__ float sm[];
    float* Xs = sm;                  // 64*68: Xs[d][c], later V[c][e]
    float* Ws = sm + 64 * 68;        // weight staging
    float* KS = sm + 2 * 64 * 68;    // Q staging, then expK[c][e]
    const int t  = threadIdx.x;
    const int b  = blockIdx.x;
    const int n  = b >> 12;
    const int hw = b & 4095;
    const size_t xbase = (size_t)n * (64ull * PLANE) + (size_t)hw * 64;

    // load X tile: 64 coalesced 256B segments (one per d)
#pragma unroll
    for (int i = 0; i < 4; i++) {
        int idx = t + i * 256;
        int d = idx >> 4, c4 = (idx & 15) << 2;
        *(float4*)(Xs + d * 68 + c4) = *(const float4*)(x + xbase + (size_t)d * PLANE + c4);
    }
    load_w(Ws, Wq, t);
    __syncthreads();

    const int cg = (t & 15) << 2;
    const int eg = (t >> 4) << 2;
    float acc[4][4];

    // ---- Q projection ----
    gemm_tile(Xs, Ws, cg, eg, acc);
    {
        float4 s4 = *(const float4*)(sq + eg);
        float4 b4 = *(const float4*)(bq + eg);
#pragma unroll
        for (int i = 0; i < 4; i++) {
            float4 y;
            y.x = lrelu(acc[i][0] * s4.x + b4.x);
            y.y = lrelu(acc[i][1] * s4.y + b4.y);
            y.z = lrelu(acc[i][2] * s4.z + b4.z);
            y.w = lrelu(acc[i][3] * s4.w + b4.w);
            *(float4*)(KS + (cg + i) * 68 + eg) = y;
        }
    }
    __syncthreads();
    // softmax over 8-channel groups (per token c, head a)
#pragma unroll
    for (int g = t; g < 512; g += 256) {
        float* row = KS + (g >> 3) * 68 + (g & 7) * 8;
        float m = row[0];
#pragma unroll
        for (int j = 1; j < 8; j++) m = fmaxf(m, row[j]);
        float e[8], s = 0.f;
#pragma unroll
        for (int j = 0; j < 8; j++) { e[j] = __expf(row[j] - m); s += e[j]; }
        float inv = 1.f / s;
#pragma unroll
        for (int j = 0; j < 8; j++) row[j] = e[j] * inv;
    }
    __syncthreads();
    // write Q rows (row t = c*4096 + hw), and stage Wk
    {
        const size_t qbase = ((size_t)n * T_TOK + hw) * 64;
#pragma unroll
        for (int i = 0; i < 4; i++) {
            int idx = t + i * 256;
            int c = idx >> 4, c4 = (idx & 15) << 2;
            *(float4*)(g_Q + qbase + (size_t)c * PLANE + c4) = *(const float4*)(KS + c * 68 + c4);
        }
    }
    load_w(Ws, Wk, t);
    __syncthreads();

    // ---- K projection -> exp ----
    gemm_tile(Xs, Ws, cg, eg, acc);
    {
        float4 s4 = *(const float4*)(sk + eg);
        float4 b4 = *(const float4*)(bk + eg);
#pragma unroll
        for (int i = 0; i < 4; i++) {
            float4 y;
            y.x = __expf(lrelu(acc[i][0] * s4.x + b4.x));
            y.y = __expf(lrelu(acc[i][1] * s4.y + b4.y));
            y.z = __expf(lrelu(acc[i][2] * s4.z + b4.z));
            y.w = __expf(lrelu(acc[i][3] * s4.w + b4.w));
            *(float4*)(KS + (cg + i) * 68 + eg) = y;
        }
    }
    __syncthreads();
    load_w(Ws, Wv, t);
    __syncthreads();

    // ---- V projection ----
    gemm_tile(Xs, Ws, cg, eg, acc);
    __syncthreads();                       // all threads done reading Xs
    {
        float4 s4 = *(const float4*)(sv + eg);
        float4 b4 = *(const float4*)(bv + eg);
#pragma unroll
        for (int i = 0; i < 4; i++) {
            float4 y;
            y.x = lrelu(acc[i][0] * s4.x + b4.x);
            y.y = lrelu(acc[i][1] * s4.y + b4.y);
            y.z = lrelu(acc[i][2] * s4.z + b4.z);
            y.w = lrelu(acc[i][3] * s4.w + b4.w);
            *(float4*)(Xs + (cg + i) * 68 + eg) = y;   // V now lives in Xs[c][e]
        }
    }
    __syncthreads();

    // ---- ctx numerator / denominator block-partials ----
#pragma unroll
    for (int g = t; g < 512; g += 256) {
        int a = g >> 6, k = (g >> 3) & 7, v = g & 7;
        const float* kp = KS + a * 8 + k;
        const float* vp = Xs + a * 8 + v;
        float s = 0.f;
#pragma unroll 8
        for (int c = 0; c < 64; c++) s += kp[c * 68] * vp[c * 68];
        atomicAdd(&g_ctxnum[n * 512 + g], s);
    }
    if (t < 64) {
        const float* kp = KS + t;
        float s = 0.f;
#pragma unroll 8
        for (int c = 0; c < 64; c++) s += kp[c * 68];
        atomicAdd(&g_den[n * 64 + t], s);
    }
}

__global__ void __launch_bounds__(256) passC_kernel(
    const float* __restrict__ x,
    const float* __restrict__ Wr, const float* __restrict__ sr, const float* __restrict__ br,
    float* __restrict__ out)
{
    __shared__ float Qs[64 * 68];     // Q rows, later aggT[e][c]
    __shared__ float Ws[64 * 68];     // Wr[e][d]
    __shared__ float ctxs[512];       // ctx[a][k][v]
    const int t  = threadIdx.x;
    const int b  = blockIdx.x;
    const int n  = b >> 12;
    const int hw = b & 4095;
    const int h  = hw >> 6, w = hw & 63;
    const size_t qn = (size_t)n * T_TOK * 64;

    // load 64 Q rows: rv = r*8+v  ->  global row r*32768 + h*512 + w*8 + v
#pragma unroll
    for (int i = 0; i < 4; i++) {
        int idx = t + i * 256;
        int rv = idx >> 4, c4 = (idx & 15) << 2;
        int r = rv >> 3, v = rv & 7;
        size_t R = (size_t)r * 32768 + h * 512 + w * 8 + v;
        *(float4*)(Qs + rv * 68 + c4) = *(const float4*)(g_Q + qn + R * 64 + c4);
    }
#pragma unroll
    for (int i = 0; i < 4; i++) {
        int idx = t + i * 256;
        int e = idx >> 4, d4 = (idx & 15) << 2;
        *(float4*)(Ws + e * 68 + d4) = *(const float4*)(Wr + e * 64 + d4);
    }
#pragma unroll
    for (int g = t; g < 512; g += 256)
        ctxs[g] = g_ctxnum[n * 512 + g] / g_den[n * 64 + (g >> 3)];
    __syncthreads();

    const int cg = (t & 15) << 2;
    const int eg = (t >> 4) << 2;
    const int a  = eg >> 3;           // head, constant over the 4-e chunk
    float acc[4][4];

    // agg[c][e=a*8+v] = sum_v' ctx[a][c/8][v'] * Q[(c%8)*8+v][a*8+v']
#pragma unroll
    for (int i = 0; i < 4; i++) {
        int c = cg + i;
        int k = c >> 3, rr = (c & 7) << 3;
        float4 cx0 = *(const float4*)(ctxs + (a * 8 + k) * 8);
        float4 cx1 = *(const float4*)(ctxs + (a * 8 + k) * 8 + 4);
#pragma unroll
        for (int j = 0; j < 4; j++) {
            int v = (eg + j) & 7;
            const float* q = Qs + (rr + v) * 68 + a * 8;
            float4 q0 = *(const float4*)q;
            float4 q1 = *(const float4*)(q + 4);
            acc[i][j] = cx0.x * q0.x + cx0.y * q0.y + cx0.z * q0.z + cx0.w * q0.w
                      + cx1.x * q1.x + cx1.y * q1.y + cx1.z * q1.z + cx1.w * q1.w;
        }
    }
    __syncthreads();
    // store transposed agg into Qs: aggT[e][c]
#pragma unroll
    for (int i = 0; i < 4; i++)
#pragma unroll
        for (int j = 0; j < 4; j++)
            Qs[(eg + j) * 68 + cg + i] = acc[i][j];
    __syncthreads();

    // rep[c][d] = sum_e aggT[e][c] * Wr[e][d]
    float r2[4][4];
#pragma unroll
    for (int i = 0; i < 4; i++)
#pragma unroll
        for (int j = 0; j < 4; j++) r2[i][j] = 0.f;
#pragma unroll 8
    for (int e = 0; e < 64; e++) {
        float4 av = *(const float4*)(Qs + e * 68 + cg);
        float4 wv = *(const float4*)(Ws + e * 68 + eg);
        r2[0][0] += av.x * wv.x; r2[0][1] += av.x * wv.y; r2[0][2] += av.x * wv.z; r2[0][3] += av.x * wv.w;
        r2[1][0] += av.y * wv.x; r2[1][1] += av.y * wv.y; r2[1][2] += av.y * wv.z; r2[1][3] += av.y * wv.w;
        r2[2][0] += av.z * wv.x; r2[2][1] += av.z * wv.y; r2[2][2] += av.z * wv.z; r2[2][3] += av.z * wv.w;
        r2[3][0] += av.w * wv.x; r2[3][1] += av.w * wv.y; r2[3][2] += av.w * wv.z; r2[3][3] += av.w * wv.w;
    }

    float4 s4 = *(const float4*)(sr + eg);
    float4 b4 = *(const float4*)(br + eg);
    float srv[4] = { s4.x, s4.y, s4.z, s4.w };
    float brv[4] = { b4.x, b4.y, b4.z, b4.w };
    const size_t ob = (size_t)n * (64ull * PLANE) + (size_t)hw * 64;
#pragma unroll
    for (int j = 0; j < 4; j++) {
        int d = eg + j;
        float4 y;
        y.x = lrelu(r2[0][j] * srv[j] + brv[j]);
        y.y = lrelu(r2[1][j] * srv[j] + brv[j]);
        y.z = lrelu(r2[2][j] * srv[j] + brv[j]);
        y.w = lrelu(r2[3][j] * srv[j] + brv[j]);
        float4 xv = *(const float4*)(x + ob + (size_t)d * PLANE + cg);
        y.x += xv.x; y.y += xv.y; y.z += xv.z; y.w += xv.w;
        *(float4*)(out + ob + (size_t)d * PLANE + cg) = y;
    }
}

extern "C" void kernel_launch(void* const* d_in, const int* in_sizes, int n_in,
                              void* d_out, int out_size) {
    const float* x  = (const float*)d_in[0];
    const float* Wk = (const float*)d_in[1];
    const float* sk = (const float*)d_in[2];
    const float* bk = (const float*)d_in[3];
    const float* Wq = (const float*)d_in[4];
    const float* sq = (const float*)d_in[5];
    const float* bq = (const float*)d_in[6];
    const float* Wv = (const float*)d_in[7];
    const float* sv = (const float*)d_in[8];
    const float* bv = (const float*)d_in[9];
    const float* Wr = (const float*)d_in[10];
    const float* sr = (const float*)d_in[11];
    const float* br = (const float*)d_in[12];
    float* out = (float*)d_out;

    const int smemA = 3 * 64 * 68 * 4;   // 52224 B
    cudaFuncSetAttribute(passA_kernel, cudaFuncAttributeMaxDynamicSharedMemorySize, smemA);

    zero_acc_kernel<<<4, 256>>>();
    passA_kernel<<<8192, 256, smemA>>>(x, Wk, sk, bk, Wq, sq, bq, Wv, sv, bv);
    passC_kernel<<<8192, 256>>>(x, Wr, sr, br, out);
}

// round 2
// speedup vs baseline: 1.0027x; 1.0027x over previous
#include <cuda_runtime.h>

// ---------------------------------------------------------------------------
// EfficientAttention: N=2, D=64, H=W=64, C=64, HEADS=8, hk=hv=8
// token t = c*4096 + h*64 + w  (T = 262144 per batch)
//
// Pass A (per (n,h,w) block, 64 tokens = all c):
//   load X tile (64 d x 64 c), GEMM vs Wq/Wk/Wv (64x64 each),
//   Q: scale/bias/lrelu + softmax over channel-groups of 8 -> g_Q
//   K: scale/bias/lrelu -> exp  (no max-subtraction: keys bounded ~|5|)
//   V: scale/bias/lrelu
//   accumulate ctx_num[a,k,v] += expK[a*8+k]*V[a*8+v], den[a,k] += expK
//   block-partial sums -> fp32 atomicAdd into tiny global accumulators.
// Pass C (per (n,h,w) block):
//   ctx = num/den; load 64 Q rows at r*32768 + h*512 + w*8 + v (8 contiguous
//   2KB chunks); agg[c][a*8+v] = sum_v' ctx[a][c/8][v'] * Q[(c%8)*8+v][a*8+v'];
//   rep = agg @ Wr, scale/bias/lrelu; out[n,d,h,w,c] = x + rep[c][d].
// ---------------------------------------------------------------------------

#define HWDIM   4096
#define T_TOK   262144
#define PLANE   262144            // HWDIM*64 floats per (n,d) plane

__device__ float g_Q[(size_t)2 * T_TOK * 64];   // 128 MiB scratch
__device__ float g_ctxnum[2 * 512];
__device__ float g_den[2 * 64];

__device__ __forceinline__ float lrelu(float y) { return y >= 0.f ? y : 0.2f * y; }

__global__ void zero_acc_kernel() {
    int t = blockIdx.x * blockDim.x + threadIdx.x;
    if (t < 2 * 512) g_ctxnum[t] = 0.f;
    if (t < 2 * 64)  g_den[t]   = 0.f;
}

// 64x64x64 sub-GEMM: out[c][e] = sum_d Xs[d][c] * Ws[d][e]; thread tile 4c x 4e
__device__ __forceinline__ void gemm_tile(const float* __restrict__ Xs,
                                          const float* __restrict__ Ws,
                                          int cg, int eg, float acc[4][4]) {
#pragma unroll
    for (int i = 0; i < 4; i++)
#pragma unroll
        for (int j = 0; j < 4; j++) acc[i][j] = 0.f;
#pragma unroll 8
    for (int d = 0; d < 64; d++) {
        float4 xv = *(const float4*)(Xs + d * 68 + cg);
        float4 wv = *(const float4*)(Ws + d * 68 + eg);
        acc[0][0] += xv.x * wv.x; acc[0][1] += xv.x * wv.y; acc[0][2] += xv.x * wv.z; acc[0][3] += xv.x * wv.w;
        acc[1][0] += xv.y * wv.x; acc[1][1] += xv.y * wv.y; acc[1][2] += xv.y * wv.z; acc[1][3] += xv.y * wv.w;
        acc[2][0] += xv.z * wv.x; acc[2][1] += xv.z * wv.y; acc[2][2] += xv.z * wv.z; acc[2][3] += xv.z * wv.w;
        acc[3][0] += xv.w * wv.x; acc[3][1] += xv.w * wv.y; acc[3][2] += xv.w * wv.z; acc[3][3] += xv.w * wv.w;
    }
}

__device__ __forceinline__ void load_w(float* __restrict__ Ws,
                                       const float* __restrict__ W, int t) {
#pragma unroll
    for (int i = 0; i < 4; i++) {
        int idx = t + i * 256;
        int d = idx >> 4, e4 = (idx & 15) << 2;
        *(float4*)(Ws + d * 68 + e4) = *(const float4*)(W + d * 64 + e4);
    }
}

__global__ void __launch_bounds__(256) passA_kernel(
    const float* __restrict__ x,
    const float* __restrict__ Wk, const float* __restrict__ sk, const float* __restrict__ bk,
    const float* __restrict__ Wq, const float* __restrict__ sq, const float* __restrict__ bq,
    const float* __restrict__ Wv, const float* __restrict__ sv, const float* __restrict__ bv)
{
    extern __shared__ float sm[];
    float* Xs = sm;                  // 64*68: Xs[d][c], later V[c][e]
    float* Ws = sm + 64 * 68;        // weight staging
    float* KS = sm + 2 * 64 * 68;    // Q staging, then expK[c][e]
    const int t  = threadIdx.x;
    const int b  = blockIdx.x;
    const int n  = b >> 12;
    const int hw = b & 4095;
    const size_t xbase = (size_t)n * (64ull * PLANE) + (size_t)hw * 64;

    // load X tile: 64 coalesced 256B segments (one per d)
#pragma unroll
    for (int i = 0; i < 4; i++) {
        int idx = t + i * 256;
        int d = idx >> 4, c4 = (idx & 15) << 2;
        *(float4*)(Xs + d * 68 + c4) = *(const float4*)(x + xbase + (size_t)d * PLANE + c4);
    }
    load_w(Ws, Wq, t);
    __syncthreads();

    const int cg = (t & 15) << 2;
    const int eg = (t >> 4) << 2;
    float acc[4][4];

    // ---- Q projection ----
    gemm_tile(Xs, Ws, cg, eg, acc);
    {
        float4 s4 = *(const float4*)(sq + eg);
        float4 b4 = *(const float4*)(bq + eg);
#pragma unroll
        for (int i = 0; i < 4; i++) {
            float4 y;
            y.x = lrelu(acc[i][0] * s4.x + b4.x);
            y.y = lrelu(acc[i][1] * s4.y + b4.y);
            y.z = lrelu(acc[i][2] * s4.z + b4.z);
            y.w = lrelu(acc[i][3] * s4.w + b4.w);
            *(float4*)(KS + (cg + i) * 68 + eg) = y;
        }
    }
    __syncthreads();
    // softmax over 8-channel groups (per token c, head a)
#pragma unroll
    for (int g = t; g < 512; g += 256) {
        float* row = KS + (g >> 3) * 68 + (g & 7) * 8;
        float m = row[0];
#pragma unroll
        for (int j = 1; j < 8; j++) m = fmaxf(m, row[j]);
        float e[8], s = 0.f;
#pragma unroll
        for (int j = 0; j < 8; j++) { e[j] = __expf(row[j] - m); s += e[j]; }
        float inv = 1.f / s;
#pragma unroll
        for (int j = 0; j < 8; j++) row[j] = e[j] * inv;
    }
    __syncthreads();
    // write Q rows (row t = c*4096 + hw), and stage Wk
    {
        const size_t qbase = ((size_t)n * T_TOK + hw) * 64;
#pragma unroll
        for (int i = 0; i < 4; i++) {
            int idx = t + i * 256;
            int c = idx >> 4, c4 = (idx & 15) << 2;
            *(float4*)(g_Q + qbase + (size_t)c * PLANE + c4) = *(const float4*)(KS + c * 68 + c4);
        }
    }
    load_w(Ws, Wk, t);
    __syncthreads();

    // ---- K projection -> exp ----
    gemm_tile(Xs, Ws, cg, eg, acc);
    {
        float4 s4 = *(const float4*)(sk + eg);
        float4 b4 = *(const float4*)(bk + eg);
#pragma unroll
        for (int i = 0; i < 4; i++) {
            float4 y;
            y.x = __expf(lrelu(acc[i][0] * s4.x + b4.x));
            y.y = __expf(lrelu(acc[i][1] * s4.y + b4.y));
            y.z = __expf(lrelu(acc[i][2] * s4.z + b4.z));
            y.w = __expf(lrelu(acc[i][3] * s4.w + b4.w));
            *(float4*)(KS + (cg + i) * 68 + eg) = y;
        }
    }
    __syncthreads();
    load_w(Ws, Wv, t);
    __syncthreads();

    // ---- V projection ----
    gemm_tile(Xs, Ws, cg, eg, acc);
    __syncthreads();                       // all threads done reading Xs
    {
        float4 s4 = *(const float4*)(sv + eg);
        float4 b4 = *(const float4*)(bv + eg);
#pragma unroll
        for (int i = 0; i < 4; i++) {
            float4 y;
            y.x = lrelu(acc[i][0] * s4.x + b4.x);
            y.y = lrelu(acc[i][1] * s4.y + b4.y);
            y.z = lrelu(acc[i][2] * s4.z + b4.z);
            y.w = lrelu(acc[i][3] * s4.w + b4.w);
            *(float4*)(Xs + (cg + i) * 68 + eg) = y;   // V now lives in Xs[c][e]
        }
    }
    __syncthreads();

    // ---- ctx numerator / denominator block-partials ----
#pragma unroll
    for (int g = t; g < 512; g += 256) {
        int a = g >> 6, k = (g >> 3) & 7, v = g & 7;
        const float* kp = KS + a * 8 + k;
        const float* vp = Xs + a * 8 + v;
        float s = 0.f;
#pragma unroll 8
        for (int c = 0; c < 64; c++) s += kp[c * 68] * vp[c * 68];
        atomicAdd(&g_ctxnum[n * 512 + g], s);
    }
    if (t < 64) {
        const float* kp = KS + t;
        float s = 0.f;
#pragma unroll 8
        for (int c = 0; c < 64; c++) s += kp[c * 68];
        atomicAdd(&g_den[n * 64 + t], s);
    }
}

__global__ void __launch_bounds__(256) passC_kernel(
    const float* __restrict__ x,
    const float* __restrict__ Wr, const float* __restrict__ sr, const float* __restrict__ br,
    float* __restrict__ out)
{
    __shared__ float Qs[64 * 68];     // Q rows, later aggT[e][c]
    __shared__ float Ws[64 * 68];     // Wr[e][d]
    __shared__ float ctxs[512];       // ctx[a][k][v]
    const int t  = threadIdx.x;
    const int b  = blockIdx.x;
    const int n  = b >> 12;
    const int hw = b & 4095;
    const int h  = hw >> 6, w = hw & 63;
    const size_t qn = (size_t)n * T_TOK * 64;

    // load 64 Q rows: rv = r*8+v  ->  global row r*32768 + h*512 + w*8 + v
#pragma unroll
    for (int i = 0; i < 4; i++) {
        int idx = t + i * 256;
        int rv = idx >> 4, c4 = (idx & 15) << 2;
        int r = rv >> 3, v = rv & 7;
        size_t R = (size_t)r * 32768 + h * 512 + w * 8 + v;
        *(float4*)(Qs + rv * 68 + c4) = *(const float4*)(g_Q + qn + R * 64 + c4);
    }
#pragma unroll
    for (int i = 0; i < 4; i++) {
        int idx = t + i * 256;
        int e = idx >> 4, d4 = (idx & 15) << 2;
        *(float4*)(Ws + e * 68 + d4) = *(const float4*)(Wr + e * 64 + d4);
    }
#pragma unroll
    for (int g = t; g < 512; g += 256)
        ctxs[g] = g_ctxnum[n * 512 + g] / g_den[n * 64 + (g >> 3)];
    __syncthreads();

    const int cg = (t & 15) << 2;
    const int eg = (t >> 4) << 2;
    const int a  = eg >> 3;           // head, constant over the 4-e chunk
    float acc[4][4];

    // agg[c][e=a*8+v] = sum_v' ctx[a][c/8][v'] * Q[(c%8)*8+v][a*8+v']
#pragma unroll
    for (int i = 0; i < 4; i++) {
        int c = cg + i;
        int k = c >> 3, rr = (c & 7) << 3;
        float4 cx0 = *(const float4*)(ctxs + (a * 8 + k) * 8);
        float4 cx1 = *(const float4*)(ctxs + (a * 8 + k) * 8 + 4);
#pragma unroll
        for (int j = 0; j < 4; j++) {
            int v = (eg + j) & 7;
            const float* q = Qs + (rr + v) * 68 + a * 8;
            float4 q0 = *(const float4*)q;
            float4 q1 = *(const float4*)(q + 4);
            acc[i][j] = cx0.x * q0.x + cx0.y * q0.y + cx0.z * q0.z + cx0.w * q0.w
                      + cx1.x * q1.x + cx1.y * q1.y + cx1.z * q1.z + cx1.w * q1.w;
        }
    }
    __syncthreads();
    // store transposed agg into Qs: aggT[e][c]
#pragma unroll
    for (int i = 0; i < 4; i++)
#pragma unroll
        for (int j = 0; j < 4; j++)
            Qs[(eg + j) * 68 + cg + i] = acc[i][j];
    __syncthreads();

    // rep[c][d] = sum_e aggT[e][c] * Wr[e][d]
    float r2[4][4];
#pragma unroll
    for (int i = 0; i < 4; i++)
#pragma unroll
        for (int j = 0; j < 4; j++) r2[i][j] = 0.f;
#pragma unroll 8
    for (int e = 0; e < 64; e++) {
        float4 av = *(const float4*)(Qs + e * 68 + cg);
        float4 wv = *(const float4*)(Ws + e * 68 + eg);
        r2[0][0] += av.x * wv.x; r2[0][1] += av.x * wv.y; r2[0][2] += av.x * wv.z; r2[0][3] += av.x * wv.w;
        r2[1][0] += av.y * wv.x; r2[1][1] += av.y * wv.y; r2[1][2] += av.y * wv.z; r2[1][3] += av.y * wv.w;
        r2[2][0] += av.z * wv.x; r2[2][1] += av.z * wv.y; r2[2][2] += av.z * wv.z; r2[2][3] += av.z * wv.w;
        r2[3][0] += av.w * wv.x; r2[3][1] += av.w * wv.y; r2[3][2] += av.w * wv.z; r2[3][3] += av.w * wv.w;
    }

    float4 s4 = *(const float4*)(sr + eg);
    float4 b4 = *(const float4*)(br + eg);
    float srv[4] = { s4.x, s4.y, s4.z, s4.w };
    float brv[4] = { b4.x, b4.y, b4.z, b4.w };
    const size_t ob = (size_t)n * (64ull * PLANE) + (size_t)hw * 64;
#pragma unroll
    for (int j = 0; j < 4; j++) {
        int d = eg + j;
        float4 y;
        y.x = lrelu(r2[0][j] * srv[j] + brv[j]);
        y.y = lrelu(r2[1][j] * srv[j] + brv[j]);
        y.z = lrelu(r2[2][j] * srv[j] + brv[j]);
        y.w = lrelu(r2[3][j] * srv[j] + brv[j]);
        float4 xv = *(const float4*)(x + ob + (size_t)d * PLANE + cg);
        y.x += xv.x; y.y += xv.y; y.z += xv.z; y.w += xv.w;
        *(float4*)(out + ob + (size_t)d * PLANE + cg) = y;
    }
}

extern "C" void kernel_launch(void* const* d_in, const int* in_sizes, int n_in,
                              void* d_out, int out_size) {
    const float* x  = (const float*)d_in[0];
    const float* Wk = (const float*)d_in[1];
    const float* sk = (const float*)d_in[2];
    const float* bk = (const float*)d_in[3];
    const float* Wq = (const float*)d_in[4];
    const float* sq = (const float*)d_in[5];
    const float* bq = (const float*)d_in[6];
    const float* Wv = (const float*)d_in[7];
    const float* sv = (const float*)d_in[8];
    const float* bv = (const float*)d_in[9];
    const float* Wr = (const float*)d_in[10];
    const float* sr = (const float*)d_in[11];
    const float* br = (const float*)d_in[12];
    float* out = (float*)d_out;

    const int smemA = 3 * 64 * 68 * 4;   // 52224 B
    cudaFuncSetAttribute(passA_kernel, cudaFuncAttributeMaxDynamicSharedMemorySize, smemA);

    zero_acc_kernel<<<4, 256>>>();
    passA_kernel<<<8192, 256, smemA>>>(x, Wk, sk, bk, Wq, sq, bq, Wv, sv, bv);
    passC_kernel<<<8192, 256>>>(x, Wr, sr, br, out);
}